// round 1
// baseline (speedup 1.0000x reference)
#include <cuda_runtime.h>
#include <math.h>

#define DMODEL 768
#define VOCAB  8192
#define HIDDEN 3072
#define NBLOCKS 4
#define NTOK   4096
#define NHEAD  12
#define DHEAD  64

// -------- scratch (static __device__ — no allocation allowed) --------
__device__ float g_X   [NTOK * DMODEL];
__device__ float g_tmp [NTOK * HIDDEN];           // FFN hidden; also reused for O
__device__ float g_F   [NTOK * DMODEL];
__device__ float g_Wvr [NBLOCKS * DMODEL * DMODEL];
__device__ float g_Watt[NBLOCKS * DMODEL * DMODEL];
__device__ float g_batt[NBLOCKS * DMODEL];

// ======================= SGEMM: C = A[MxK] @ B[KxN] (+bias, opt relu) =======================
// BM=BN=128, BK=16, 256 threads, 8x8 per thread. All M,N,K here are multiples of tile sizes.
template<int RELU>
__global__ void __launch_bounds__(256) sgemm_kernel(
    const float* __restrict__ A, const float* __restrict__ B,
    const float* __restrict__ bias, float* __restrict__ C,
    int M, int N, int K)
{
    __shared__ float As[16][128];
    __shared__ float Bs[16][128];

    const int tid = threadIdx.x;
    const int tx = tid & 15;          // N direction
    const int ty = tid >> 4;          // M direction

    const int rowC = blockIdx.y * 128 + ty * 8;
    const int colC = blockIdx.x * 128 + tx * 8;

    float acc[8][8];
    #pragma unroll
    for (int i = 0; i < 8; i++)
        #pragma unroll
        for (int j = 0; j < 8; j++) acc[i][j] = 0.f;

    // A tile loader indices: 128 rows x 16 cols, 2 x float4 per thread
    const int aRow = tid >> 2;            // 0..63
    const int aCol = (tid & 3) * 4;       // 0,4,8,12
    // B tile loader indices: 16 rows x 128 cols, 2 x float4 per thread
    const int bRow = tid >> 5;            // 0..7
    const int bCol = (tid & 31) * 4;      // 0..124

    const float* Abase = A + (size_t)(blockIdx.y * 128) * K;
    const float* Bbase = B + blockIdx.x * 128;

    for (int kt = 0; kt < K; kt += 16) {
        #pragma unroll
        for (int r = 0; r < 2; r++) {
            const int ar = aRow + r * 64;
            float4 va = *reinterpret_cast<const float4*>(Abase + (size_t)ar * K + kt + aCol);
            As[aCol + 0][ar] = va.x;
            As[aCol + 1][ar] = va.y;
            As[aCol + 2][ar] = va.z;
            As[aCol + 3][ar] = va.w;
        }
        #pragma unroll
        for (int r = 0; r < 2; r++) {
            const int br = bRow + r * 8;
            float4 vb = *reinterpret_cast<const float4*>(Bbase + (size_t)(kt + br) * N + bCol);
            *reinterpret_cast<float4*>(&Bs[br][bCol]) = vb;
        }
        __syncthreads();

        #pragma unroll
        for (int k = 0; k < 16; k++) {
            float4 a0 = *reinterpret_cast<const float4*>(&As[k][ty * 8]);
            float4 a1 = *reinterpret_cast<const float4*>(&As[k][ty * 8 + 4]);
            float4 b0 = *reinterpret_cast<const float4*>(&Bs[k][tx * 8]);
            float4 b1 = *reinterpret_cast<const float4*>(&Bs[k][tx * 8 + 4]);
            float ra[8] = {a0.x, a0.y, a0.z, a0.w, a1.x, a1.y, a1.z, a1.w};
            float rb[8] = {b0.x, b0.y, b0.z, b0.w, b1.x, b1.y, b1.z, b1.w};
            #pragma unroll
            for (int i = 0; i < 8; i++)
                #pragma unroll
                for (int j = 0; j < 8; j++)
                    acc[i][j] += ra[i] * rb[j];
        }
        __syncthreads();
    }

    float bb[8];
    #pragma unroll
    for (int j = 0; j < 8; j++) bb[j] = bias ? bias[colC + j] : 0.f;

    #pragma unroll
    for (int i = 0; i < 8; i++) {
        float* cp = C + (size_t)(rowC + i) * N + colC;
        float4 o0, o1;
        float v[8];
        #pragma unroll
        for (int j = 0; j < 8; j++) {
            float t = acc[i][j] + bb[j];
            if (RELU) t = fmaxf(t, 0.f);
            v[j] = t;
        }
        o0 = make_float4(v[0], v[1], v[2], v[3]);
        o1 = make_float4(v[4], v[5], v[6], v[7]);
        *reinterpret_cast<float4*>(cp)     = o0;
        *reinterpret_cast<float4*>(cp + 4) = o1;
    }
}

// ======================= weight prep =======================
// Wv (NB,H,D,DK) -> Wvr[i][d][h*DK+e] contiguous [D, H*DK]
__global__ void prep_wv(const float* __restrict__ Wv, float* __restrict__ Wvr) {
    int idx = blockIdx.x * blockDim.x + threadIdx.x;
    if (idx >= NBLOCKS * DMODEL * DMODEL) return;
    int i   = idx / (DMODEL * DMODEL);
    int rem = idx % (DMODEL * DMODEL);
    int d   = rem / DMODEL;
    int c   = rem % DMODEL;
    int h = c / DHEAD, e = c % DHEAD;
    Wvr[idx] = Wv[(((size_t)i * NHEAD + h) * DMODEL + d) * DHEAD + e];
}

// batt[i][j] = bo[i][j] + sum_c bv[i][c] * Wo[i][c][j]
__global__ void prep_batt(const float* __restrict__ bv, const float* __restrict__ Wo,
                          const float* __restrict__ bo, float* __restrict__ batt) {
    int i = blockIdx.y;
    int j = blockIdx.x * blockDim.x + threadIdx.x;
    if (j >= DMODEL) return;
    const float* w = Wo + (size_t)i * DMODEL * DMODEL;
    const float* b = bv + (size_t)i * DMODEL;
    float s = bo[(size_t)i * DMODEL + j];
    for (int c = 0; c < DMODEL; c++) s += b[c] * w[(size_t)c * DMODEL + j];
    batt[(size_t)i * DMODEL + j] = s;
}

// ======================= add + layernorm (population var, no eps, no affine) =======================
__device__ __forceinline__ float block_reduce_sum(float v, float* sh) {
    #pragma unroll
    for (int o = 16; o > 0; o >>= 1) v += __shfl_xor_sync(0xffffffffu, v, o);
    __syncthreads();                       // protect sh reuse across calls
    if ((threadIdx.x & 31) == 0) sh[threadIdx.x >> 5] = v;
    __syncthreads();
    float t = (threadIdx.x < 8) ? sh[threadIdx.x] : 0.f;
    if (threadIdx.x < 32) {
        #pragma unroll
        for (int o = 4; o > 0; o >>= 1) t += __shfl_xor_sync(0xffffffffu, t, o);
        if (threadIdx.x == 0) sh[0] = t;
    }
    __syncthreads();
    return sh[0];
}

__global__ void __launch_bounds__(256) add_ln(float* __restrict__ X, const float* __restrict__ O) {
    __shared__ float sh[8];
    const size_t base = (size_t)blockIdx.x * DMODEL;
    float v[3];
    float s = 0.f;
    #pragma unroll
    for (int j = 0; j < 3; j++) {
        int c = threadIdx.x + j * 256;
        float t = X[base + c] + O[base + c];
        v[j] = t; s += t;
    }
    float mu = block_reduce_sum(s, sh) * (1.f / DMODEL);
    float q = 0.f;
    #pragma unroll
    for (int j = 0; j < 3; j++) { float d = v[j] - mu; q += d * d; }
    float var = block_reduce_sum(q, sh) * (1.f / DMODEL);
    float inv = rsqrtf(var);
    #pragma unroll
    for (int j = 0; j < 3; j++) {
        int c = threadIdx.x + j * 256;
        X[base + c] = (v[j] - mu) * inv;
    }
}

// ======================= row softmax over VOCAB =======================
__global__ void __launch_bounds__(256) softmax_rows(float* __restrict__ X) {
    __shared__ float sh[8];
    const size_t base = (size_t)blockIdx.x * VOCAB;
    float v[32];
    float m = -INFINITY;
    #pragma unroll
    for (int j = 0; j < 32; j++) {
        v[j] = X[base + threadIdx.x + j * 256];
        m = fmaxf(m, v[j]);
    }
    // block max
    #pragma unroll
    for (int o = 16; o > 0; o >>= 1) m = fmaxf(m, __shfl_xor_sync(0xffffffffu, m, o));
    if ((threadIdx.x & 31) == 0) sh[threadIdx.x >> 5] = m;
    __syncthreads();
    float mm = (threadIdx.x < 8) ? sh[threadIdx.x] : -INFINITY;
    if (threadIdx.x < 32) {
        #pragma unroll
        for (int o = 4; o > 0; o >>= 1) mm = fmaxf(mm, __shfl_xor_sync(0xffffffffu, mm, o));
        if (threadIdx.x == 0) sh[0] = mm;
    }
    __syncthreads();
    m = sh[0];
    __syncthreads();

    float s = 0.f;
    #pragma unroll
    for (int j = 0; j < 32; j++) { v[j] = expf(v[j] - m); s += v[j]; }
    float tot = block_reduce_sum(s, sh);
    float inv = 1.f / tot;
    #pragma unroll
    for (int j = 0; j < 32; j++) X[base + threadIdx.x + j * 256] = v[j] * inv;
}

// ======================= launch =======================
extern "C" void kernel_launch(void* const* d_in, const int* in_sizes, int n_in,
                              void* d_out, int out_size) {
    const float* Xin   = (const float*)d_in[0];
    const float* emb_w = (const float*)d_in[1];
    const float* emb_b = (const float*)d_in[2];
    // d_in[3..6] = Wq,bq,Wk,bk — mathematically unused (softmax row-sum == 1)
    const float* Wv    = (const float*)d_in[7];
    const float* bv    = (const float*)d_in[8];
    const float* Wo    = (const float*)d_in[9];
    const float* bo    = (const float*)d_in[10];
    const float* W1    = (const float*)d_in[11];
    const float* b1    = (const float*)d_in[12];
    const float* W2    = (const float*)d_in[13];
    const float* b2    = (const float*)d_in[14];
    const float* Wout  = (const float*)d_in[15];
    const float* bout  = (const float*)d_in[16];
    float* out = (float*)d_out;

    float *pX, *pTmp, *pF, *pWvr, *pWatt, *pBatt;
    cudaGetSymbolAddress((void**)&pX,    g_X);
    cudaGetSymbolAddress((void**)&pTmp,  g_tmp);
    cudaGetSymbolAddress((void**)&pF,    g_F);
    cudaGetSymbolAddress((void**)&pWvr,  g_Wvr);
    cudaGetSymbolAddress((void**)&pWatt, g_Watt);
    cudaGetSymbolAddress((void**)&pBatt, g_batt);

    // ---- fuse attention weights: Watt[i] = Wv_r[i] @ Wo[i]; batt[i] = bv[i]@Wo[i] + bo[i] ----
    prep_wv<<<(NBLOCKS * DMODEL * DMODEL + 255) / 256, 256>>>(Wv, pWvr);
    prep_batt<<<dim3(DMODEL / 256, NBLOCKS), 256>>>(bv, Wo, bo, pBatt);
    for (int i = 0; i < NBLOCKS; i++) {
        sgemm_kernel<0><<<dim3(DMODEL / 128, DMODEL / 128), 256>>>(
            pWvr + (size_t)i * DMODEL * DMODEL, Wo + (size_t)i * DMODEL * DMODEL,
            nullptr, pWatt + (size_t)i * DMODEL * DMODEL, DMODEL, DMODEL, DMODEL);
    }

    // ---- embedding: X = Xin @ emb_w + emb_b ----
    sgemm_kernel<0><<<dim3(DMODEL / 128, NTOK / 128), 256>>>(
        Xin, emb_w, emb_b, pX, NTOK, DMODEL, VOCAB);

    // ---- 4 transformer blocks (attention == fused V->O projection) ----
    for (int i = 0; i < NBLOCKS; i++) {
        sgemm_kernel<0><<<dim3(DMODEL / 128, NTOK / 128), 256>>>(
            pX, pWatt + (size_t)i * DMODEL * DMODEL, pBatt + (size_t)i * DMODEL,
            pTmp, NTOK, DMODEL, DMODEL);
        add_ln<<<NTOK, 256>>>(pX, pTmp);

        sgemm_kernel<1><<<dim3(HIDDEN / 128, NTOK / 128), 256>>>(
            pX, W1 + (size_t)i * DMODEL * HIDDEN, b1 + (size_t)i * HIDDEN,
            pTmp, NTOK, HIDDEN, DMODEL);
        sgemm_kernel<0><<<dim3(DMODEL / 128, NTOK / 128), 256>>>(
            pTmp, W2 + (size_t)i * HIDDEN * DMODEL, b2 + (size_t)i * DMODEL,
            pF, NTOK, DMODEL, HIDDEN);
        add_ln<<<NTOK, 256>>>(pX, pF);
    }

    // ---- output head + softmax (in-place on d_out) ----
    sgemm_kernel<0><<<dim3(VOCAB / 128, NTOK / 128), 256>>>(
        pX, Wout, bout, out, NTOK, VOCAB, DMODEL);
    softmax_rows<<<NTOK, 256>>>(out);
}

// round 2
// speedup vs baseline: 1.0010x; 1.0010x over previous
#include <cuda_runtime.h>
#include <math.h>

#define DMODEL 768
#define VOCAB  8192
#define HIDDEN 3072
#define NBLOCKS 4
#define NTOK   4096
#define NHEAD  12
#define DHEAD  64

// -------- scratch (static __device__ — no allocation allowed) --------
__device__ float g_X   [NTOK * DMODEL];
__device__ float g_tmp [NTOK * HIDDEN];           // FFN hidden; also reused for O
__device__ float g_F   [NTOK * DMODEL];
__device__ float g_Wvr [NBLOCKS * DMODEL * DMODEL];
__device__ float g_Watt[NBLOCKS * DMODEL * DMODEL];
__device__ float g_batt[NBLOCKS * DMODEL];

// ======================= SGEMM: C = A[MxK] @ B[KxN] (+bias, opt relu) =======================
// BM=BN=128, BK=16, 256 threads, 8x8 per thread. All M,N,K here are multiples of tile sizes.
template<int RELU>
__global__ void __launch_bounds__(256) sgemm_kernel(
    const float* __restrict__ A, const float* __restrict__ B,
    const float* __restrict__ bias, float* __restrict__ C,
    int M, int N, int K)
{
    __shared__ float As[16][128];
    __shared__ float Bs[16][128];

    const int tid = threadIdx.x;
    const int tx = tid & 15;          // N direction
    const int ty = tid >> 4;          // M direction

    const int rowC = blockIdx.y * 128 + ty * 8;
    const int colC = blockIdx.x * 128 + tx * 8;

    float acc[8][8];
    #pragma unroll
    for (int i = 0; i < 8; i++)
        #pragma unroll
        for (int j = 0; j < 8; j++) acc[i][j] = 0.f;

    // A tile loader indices: 128 rows x 16 cols, 2 x float4 per thread
    const int aRow = tid >> 2;            // 0..63
    const int aCol = (tid & 3) * 4;       // 0,4,8,12
    // B tile loader indices: 16 rows x 128 cols, 2 x float4 per thread
    const int bRow = tid >> 5;            // 0..7
    const int bCol = (tid & 31) * 4;      // 0..124

    const float* Abase = A + (size_t)(blockIdx.y * 128) * K;
    const float* Bbase = B + blockIdx.x * 128;

    for (int kt = 0; kt < K; kt += 16) {
        #pragma unroll
        for (int r = 0; r < 2; r++) {
            const int ar = aRow + r * 64;
            float4 va = *reinterpret_cast<const float4*>(Abase + (size_t)ar * K + kt + aCol);
            As[aCol + 0][ar] = va.x;
            As[aCol + 1][ar] = va.y;
            As[aCol + 2][ar] = va.z;
            As[aCol + 3][ar] = va.w;
        }
        #pragma unroll
        for (int r = 0; r < 2; r++) {
            const int br = bRow + r * 8;
            float4 vb = *reinterpret_cast<const float4*>(Bbase + (size_t)(kt + br) * N + bCol);
            *reinterpret_cast<float4*>(&Bs[br][bCol]) = vb;
        }
        __syncthreads();

        #pragma unroll
        for (int k = 0; k < 16; k++) {
            float4 a0 = *reinterpret_cast<const float4*>(&As[k][ty * 8]);
            float4 a1 = *reinterpret_cast<const float4*>(&As[k][ty * 8 + 4]);
            float4 b0 = *reinterpret_cast<const float4*>(&Bs[k][tx * 8]);
            float4 b1 = *reinterpret_cast<const float4*>(&Bs[k][tx * 8 + 4]);
            float ra[8] = {a0.x, a0.y, a0.z, a0.w, a1.x, a1.y, a1.z, a1.w};
            float rb[8] = {b0.x, b0.y, b0.z, b0.w, b1.x, b1.y, b1.z, b1.w};
            #pragma unroll
            for (int i = 0; i < 8; i++)
                #pragma unroll
                for (int j = 0; j < 8; j++)
                    acc[i][j] += ra[i] * rb[j];
        }
        __syncthreads();
    }

    float bb[8];
    #pragma unroll
    for (int j = 0; j < 8; j++) bb[j] = bias ? bias[colC + j] : 0.f;

    #pragma unroll
    for (int i = 0; i < 8; i++) {
        float* cp = C + (size_t)(rowC + i) * N + colC;
        float4 o0, o1;
        float v[8];
        #pragma unroll
        for (int j = 0; j < 8; j++) {
            float t = acc[i][j] + bb[j];
            if (RELU) t = fmaxf(t, 0.f);
            v[j] = t;
        }
        o0 = make_float4(v[0], v[1], v[2], v[3]);
        o1 = make_float4(v[4], v[5], v[6], v[7]);
        *reinterpret_cast<float4*>(cp)     = o0;
        *reinterpret_cast<float4*>(cp + 4) = o1;
    }
}

// ======================= weight prep =======================
// Wv (NB,H,D,DK) -> Wvr[i][d][h*DK+e] contiguous [D, H*DK]
__global__ void prep_wv(const float* __restrict__ Wv, float* __restrict__ Wvr) {
    int idx = blockIdx.x * blockDim.x + threadIdx.x;
    if (idx >= NBLOCKS * DMODEL * DMODEL) return;
    int i   = idx / (DMODEL * DMODEL);
    int rem = idx % (DMODEL * DMODEL);
    int d   = rem / DMODEL;
    int c   = rem % DMODEL;
    int h = c / DHEAD, e = c % DHEAD;
    Wvr[idx] = Wv[(((size_t)i * NHEAD + h) * DMODEL + d) * DHEAD + e];
}

// batt[i][j] = bo[i][j] + sum_c bv[i][c] * Wo[i][c][j]
__global__ void prep_batt(const float* __restrict__ bv, const float* __restrict__ Wo,
                          const float* __restrict__ bo, float* __restrict__ batt) {
    int i = blockIdx.y;
    int j = blockIdx.x * blockDim.x + threadIdx.x;
    if (j >= DMODEL) return;
    const float* w = Wo + (size_t)i * DMODEL * DMODEL;
    const float* b = bv + (size_t)i * DMODEL;
    float s = bo[(size_t)i * DMODEL + j];
    for (int c = 0; c < DMODEL; c++) s += b[c] * w[(size_t)c * DMODEL + j];
    batt[(size_t)i * DMODEL + j] = s;
}

// ======================= add + layernorm (population var, no eps, no affine) =======================
__device__ __forceinline__ float block_reduce_sum(float v, float* sh) {
    #pragma unroll
    for (int o = 16; o > 0; o >>= 1) v += __shfl_xor_sync(0xffffffffu, v, o);
    __syncthreads();                       // protect sh reuse across calls
    if ((threadIdx.x & 31) == 0) sh[threadIdx.x >> 5] = v;
    __syncthreads();
    float t = (threadIdx.x < 8) ? sh[threadIdx.x] : 0.f;
    if (threadIdx.x < 32) {
        #pragma unroll
        for (int o = 4; o > 0; o >>= 1) t += __shfl_xor_sync(0xffffffffu, t, o);
        if (threadIdx.x == 0) sh[0] = t;
    }
    __syncthreads();
    return sh[0];
}

__global__ void __launch_bounds__(256) add_ln(float* __restrict__ X, const float* __restrict__ O) {
    __shared__ float sh[8];
    const size_t base = (size_t)blockIdx.x * DMODEL;
    float v[3];
    float s = 0.f;
    #pragma unroll
    for (int j = 0; j < 3; j++) {
        int c = threadIdx.x + j * 256;
        float t = X[base + c] + O[base + c];
        v[j] = t; s += t;
    }
    float mu = block_reduce_sum(s, sh) * (1.f / DMODEL);
    float q = 0.f;
    #pragma unroll
    for (int j = 0; j < 3; j++) { float d = v[j] - mu; q += d * d; }
    float var = block_reduce_sum(q, sh) * (1.f / DMODEL);
    float inv = rsqrtf(var);
    #pragma unroll
    for (int j = 0; j < 3; j++) {
        int c = threadIdx.x + j * 256;
        X[base + c] = (v[j] - mu) * inv;
    }
}

// ======================= row softmax over VOCAB =======================
__global__ void __launch_bounds__(256) softmax_rows(float* __restrict__ X) {
    __shared__ float sh[8];
    const size_t base = (size_t)blockIdx.x * VOCAB;
    float v[32];
    float m = -INFINITY;
    #pragma unroll
    for (int j = 0; j < 32; j++) {
        v[j] = X[base + threadIdx.x + j * 256];
        m = fmaxf(m, v[j]);
    }
    // block max
    #pragma unroll
    for (int o = 16; o > 0; o >>= 1) m = fmaxf(m, __shfl_xor_sync(0xffffffffu, m, o));
    if ((threadIdx.x & 31) == 0) sh[threadIdx.x >> 5] = m;
    __syncthreads();
    float mm = (threadIdx.x < 8) ? sh[threadIdx.x] : -INFINITY;
    if (threadIdx.x < 32) {
        #pragma unroll
        for (int o = 4; o > 0; o >>= 1) mm = fmaxf(mm, __shfl_xor_sync(0xffffffffu, mm, o));
        if (threadIdx.x == 0) sh[0] = mm;
    }
    __syncthreads();
    m = sh[0];
    __syncthreads();

    float s = 0.f;
    #pragma unroll
    for (int j = 0; j < 32; j++) { v[j] = expf(v[j] - m); s += v[j]; }
    float tot = block_reduce_sum(s, sh);
    float inv = 1.f / tot;
    #pragma unroll
    for (int j = 0; j < 32; j++) X[base + threadIdx.x + j * 256] = v[j] * inv;
}

// ======================= launch =======================
extern "C" void kernel_launch(void* const* d_in, const int* in_sizes, int n_in,
                              void* d_out, int out_size) {
    const float* Xin   = (const float*)d_in[0];
    const float* emb_w = (const float*)d_in[1];
    const float* emb_b = (const float*)d_in[2];
    // d_in[3..6] = Wq,bq,Wk,bk — mathematically unused (softmax row-sum == 1)
    const float* Wv    = (const float*)d_in[7];
    const float* bv    = (const float*)d_in[8];
    const float* Wo    = (const float*)d_in[9];
    const float* bo    = (const float*)d_in[10];
    const float* W1    = (const float*)d_in[11];
    const float* b1    = (const float*)d_in[12];
    const float* W2    = (const float*)d_in[13];
    const float* b2    = (const float*)d_in[14];
    const float* Wout  = (const float*)d_in[15];
    const float* bout  = (const float*)d_in[16];
    float* out = (float*)d_out;

    float *pX, *pTmp, *pF, *pWvr, *pWatt, *pBatt;
    cudaGetSymbolAddress((void**)&pX,    g_X);
    cudaGetSymbolAddress((void**)&pTmp,  g_tmp);
    cudaGetSymbolAddress((void**)&pF,    g_F);
    cudaGetSymbolAddress((void**)&pWvr,  g_Wvr);
    cudaGetSymbolAddress((void**)&pWatt, g_Watt);
    cudaGetSymbolAddress((void**)&pBatt, g_batt);

    // ---- fuse attention weights: Watt[i] = Wv_r[i] @ Wo[i]; batt[i] = bv[i]@Wo[i] + bo[i] ----
    prep_wv<<<(NBLOCKS * DMODEL * DMODEL + 255) / 256, 256>>>(Wv, pWvr);
    prep_batt<<<dim3(DMODEL / 256, NBLOCKS), 256>>>(bv, Wo, bo, pBatt);
    for (int i = 0; i < NBLOCKS; i++) {
        sgemm_kernel<0><<<dim3(DMODEL / 128, DMODEL / 128), 256>>>(
            pWvr + (size_t)i * DMODEL * DMODEL, Wo + (size_t)i * DMODEL * DMODEL,
            nullptr, pWatt + (size_t)i * DMODEL * DMODEL, DMODEL, DMODEL, DMODEL);
    }

    // ---- embedding: X = Xin @ emb_w + emb_b ----
    sgemm_kernel<0><<<dim3(DMODEL / 128, NTOK / 128), 256>>>(
        Xin, emb_w, emb_b, pX, NTOK, DMODEL, VOCAB);

    // ---- 4 transformer blocks (attention == fused V->O projection) ----
    for (int i = 0; i < NBLOCKS; i++) {
        sgemm_kernel<0><<<dim3(DMODEL / 128, NTOK / 128), 256>>>(
            pX, pWatt + (size_t)i * DMODEL * DMODEL, pBatt + (size_t)i * DMODEL,
            pTmp, NTOK, DMODEL, DMODEL);
        add_ln<<<NTOK, 256>>>(pX, pTmp);

        sgemm_kernel<1><<<dim3(HIDDEN / 128, NTOK / 128), 256>>>(
            pX, W1 + (size_t)i * DMODEL * HIDDEN, b1 + (size_t)i * HIDDEN,
            pTmp, NTOK, HIDDEN, DMODEL);
        sgemm_kernel<0><<<dim3(DMODEL / 128, NTOK / 128), 256>>>(
            pTmp, W2 + (size_t)i * HIDDEN * DMODEL, b2 + (size_t)i * DMODEL,
            pF, NTOK, DMODEL, HIDDEN);
        add_ln<<<NTOK, 256>>>(pX, pF);
    }

    // ---- output head + softmax (in-place on d_out) ----
    sgemm_kernel<0><<<dim3(VOCAB / 128, NTOK / 128), 256>>>(
        pX, Wout, bout, out, NTOK, VOCAB, DMODEL);
    softmax_rows<<<NTOK, 256>>>(out);
}

// round 3
// speedup vs baseline: 1.3782x; 1.3768x over previous
#include <cuda_runtime.h>
#include <math.h>
#include <stdint.h>

#define DMODEL 768
#define VOCAB  8192
#define HIDDEN 3072
#define NBLOCKS 4
#define NTOK   4096
#define NHEAD  12
#define DHEAD  64

// -------- scratch (static __device__ — no allocation allowed) --------
__device__ float g_X   [NTOK * DMODEL];
__device__ float g_tmp [NTOK * HIDDEN];
__device__ float g_F   [NTOK * DMODEL];
__device__ float g_Wvr [NBLOCKS * DMODEL * DMODEL];
__device__ float g_Watt[NBLOCKS * DMODEL * DMODEL];
__device__ float g_batt[NBLOCKS * DMODEL];

// ======================= tf32 helpers =======================
__device__ __forceinline__ uint32_t f2tf(float f) {
    uint32_t u;
    asm("cvt.rna.tf32.f32 %0, %1;" : "=r"(u) : "f"(f));
    return u;
}

__device__ __forceinline__ void mma_tf32(float* c, const uint32_t* a, const uint32_t* b) {
    asm volatile("mma.sync.aligned.m16n8k8.row.col.f32.tf32.tf32.f32 "
                 "{%0,%1,%2,%3}, {%4,%5,%6,%7}, {%8,%9}, {%0,%1,%2,%3};"
                 : "+f"(c[0]), "+f"(c[1]), "+f"(c[2]), "+f"(c[3])
                 : "r"(a[0]), "r"(a[1]), "r"(a[2]), "r"(a[3]),
                   "r"(b[0]), "r"(b[1]));
}

__device__ __forceinline__ void cp16(void* smem, const void* gmem) {
    uint32_t s = (uint32_t)__cvta_generic_to_shared(smem);
    asm volatile("cp.async.cg.shared.global [%0], [%1], 16;" :: "r"(s), "l"(gmem));
}
__device__ __forceinline__ void cp_commit() { asm volatile("cp.async.commit_group;"); }
template<int W> __device__ __forceinline__ void cp_wait() {
    asm volatile("cp.async.wait_group %0;" :: "n"(W));
    }

// ======================= GEMM: C = A[MxK] @ B[KxN] (+bias, opt relu) =======================
// 128x128x16 tiles, 8 warps, warp tile 32x64, mma.m16n8k8.tf32, 3-pass tf32 split.
// M,N multiples of 128; K multiple of 16.
#define BK 16
#define ASTR 20    // 16 + 4 pad (words) -> conflict-free A frag loads
#define BSTR 136   // 128 + 8 pad       -> conflict-free B frag loads

template<int RELU, int BATCHED>
__global__ void __launch_bounds__(256) gemm_tf32(
    const float* __restrict__ A, const float* __restrict__ B,
    const float* __restrict__ bias, float* __restrict__ C,
    int M, int N, int K)
{
    __shared__ float As[2][128][ASTR];  // 20.0 KB
    __shared__ float Bs[2][BK][BSTR];   // 17.0 KB

    if (BATCHED) {
        size_t z = blockIdx.z;
        A += z * (size_t)M * K;
        B += z * (size_t)K * N;
        C += z * (size_t)M * N;
    }

    const int tid  = threadIdx.x;
    const int lane = tid & 31;
    const int wid  = tid >> 5;
    const int wm   = wid & 3;     // 0..3 (M)
    const int wn   = wid >> 2;    // 0..1 (N)

    const float* Ab = A + (size_t)(blockIdx.y * 128) * K;
    const float* Bb = B + blockIdx.x * 128;

    // loader indices
    const int aRow = tid >> 2;            // 0..63 (use +0/+64? no: l=tid,tid+256 -> row=l>>2)
    (void)aRow;

    auto load_stage = [&](int s, int kt) {
        #pragma unroll
        for (int i = 0; i < 2; i++) {
            int l = tid + i * 256;              // 0..511
            int row = l >> 2;                   // 0..127
            int c4  = (l & 3) * 4;              // 0,4,8,12
            cp16(&As[s][row][c4], Ab + (size_t)row * K + kt + c4);
        }
        #pragma unroll
        for (int i = 0; i < 2; i++) {
            int l = tid + i * 256;
            int row = l >> 5;                   // 0..15
            int c4  = (l & 31) * 4;             // 0..124
            cp16(&Bs[s][row][c4], Bb + (size_t)(kt + row) * N + c4);
        }
        cp_commit();
    };

    float acc[2][8][4];
    #pragma unroll
    for (int i = 0; i < 2; i++)
        #pragma unroll
        for (int j = 0; j < 8; j++)
            #pragma unroll
            for (int k = 0; k < 4; k++) acc[i][j][k] = 0.f;

    const int rbase = wm * 32 + (lane >> 2);
    const int cbase = wn * 64 + (lane >> 2);
    const int kq    = lane & 3;

    load_stage(0, 0);
    const int nk = K / BK;

    for (int t = 0; t < nk; t++) {
        if (t + 1 < nk) { load_stage((t + 1) & 1, (t + 1) * BK); cp_wait<1>(); }
        else            { cp_wait<0>(); }
        __syncthreads();

        const int s = t & 1;
        #pragma unroll
        for (int kk = 0; kk < 2; kk++) {
            const int k0 = kk * 8;
            float fa[2][4], fb[8][2];
            #pragma unroll
            for (int mt = 0; mt < 2; mt++) {
                int r = rbase + mt * 16;
                fa[mt][0] = As[s][r    ][k0 + kq];
                fa[mt][1] = As[s][r + 8][k0 + kq];
                fa[mt][2] = As[s][r    ][k0 + 4 + kq];
                fa[mt][3] = As[s][r + 8][k0 + 4 + kq];
            }
            #pragma unroll
            for (int nt = 0; nt < 8; nt++) {
                int c = cbase + nt * 8;
                fb[nt][0] = Bs[s][k0 + kq][c];
                fb[nt][1] = Bs[s][k0 + 4 + kq][c];
            }

            uint32_t ba[2][4], bb[8][2];
            #pragma unroll
            for (int mt = 0; mt < 2; mt++)
                #pragma unroll
                for (int v = 0; v < 4; v++) ba[mt][v] = f2tf(fa[mt][v]);
            #pragma unroll
            for (int nt = 0; nt < 8; nt++)
                #pragma unroll
                for (int v = 0; v < 2; v++) bb[nt][v] = f2tf(fb[nt][v]);

            // pass 1: big*big
            #pragma unroll
            for (int mt = 0; mt < 2; mt++)
                #pragma unroll
                for (int nt = 0; nt < 8; nt++)
                    mma_tf32(acc[mt][nt], ba[mt], bb[nt]);

            // pass 2: smallA * bigB
            uint32_t sa[2][4];
            #pragma unroll
            for (int mt = 0; mt < 2; mt++)
                #pragma unroll
                for (int v = 0; v < 4; v++)
                    sa[mt][v] = f2tf(fa[mt][v] - __uint_as_float(ba[mt][v]));
            #pragma unroll
            for (int mt = 0; mt < 2; mt++)
                #pragma unroll
                for (int nt = 0; nt < 8; nt++)
                    mma_tf32(acc[mt][nt], sa[mt], bb[nt]);

            // pass 3: bigA * smallB
            uint32_t sb[8][2];
            #pragma unroll
            for (int nt = 0; nt < 8; nt++)
                #pragma unroll
                for (int v = 0; v < 2; v++)
                    sb[nt][v] = f2tf(fb[nt][v] - __uint_as_float(bb[nt][v]));
            #pragma unroll
            for (int mt = 0; mt < 2; mt++)
                #pragma unroll
                for (int nt = 0; nt < 8; nt++)
                    mma_tf32(acc[mt][nt], ba[mt], sb[nt]);
        }
        __syncthreads();
    }

    // epilogue
    const int rowC = blockIdx.y * 128 + wm * 32 + (lane >> 2);
    const int colC = blockIdx.x * 128 + wn * 64 + (lane & 3) * 2;
    float bv[8][2];
    #pragma unroll
    for (int nt = 0; nt < 8; nt++) {
        bv[nt][0] = bias ? bias[colC + nt * 8]     : 0.f;
        bv[nt][1] = bias ? bias[colC + nt * 8 + 1] : 0.f;
    }
    #pragma unroll
    for (int mt = 0; mt < 2; mt++) {
        int r0 = rowC + mt * 16;
        #pragma unroll
        for (int nt = 0; nt < 8; nt++) {
            int c = colC + nt * 8;
            float v00 = acc[mt][nt][0] + bv[nt][0];
            float v01 = acc[mt][nt][1] + bv[nt][1];
            float v10 = acc[mt][nt][2] + bv[nt][0];
            float v11 = acc[mt][nt][3] + bv[nt][1];
            if (RELU) {
                v00 = fmaxf(v00, 0.f); v01 = fmaxf(v01, 0.f);
                v10 = fmaxf(v10, 0.f); v11 = fmaxf(v11, 0.f);
            }
            *reinterpret_cast<float2*>(C + (size_t)r0 * N + c)       = make_float2(v00, v01);
            *reinterpret_cast<float2*>(C + (size_t)(r0 + 8) * N + c) = make_float2(v10, v11);
        }
    }
}

// ======================= weight prep =======================
__global__ void prep_wv(const float* __restrict__ Wv, float* __restrict__ Wvr) {
    int idx = blockIdx.x * blockDim.x + threadIdx.x;
    if (idx >= NBLOCKS * DMODEL * DMODEL) return;
    int i   = idx / (DMODEL * DMODEL);
    int rem = idx % (DMODEL * DMODEL);
    int d   = rem / DMODEL;
    int c   = rem % DMODEL;
    int h = c / DHEAD, e = c % DHEAD;
    Wvr[idx] = Wv[(((size_t)i * NHEAD + h) * DMODEL + d) * DHEAD + e];
}

__global__ void prep_batt(const float* __restrict__ bv, const float* __restrict__ Wo,
                          const float* __restrict__ bo, float* __restrict__ batt) {
    int i = blockIdx.y;
    int j = blockIdx.x * blockDim.x + threadIdx.x;
    if (j >= DMODEL) return;
    const float* w = Wo + (size_t)i * DMODEL * DMODEL;
    const float* b = bv + (size_t)i * DMODEL;
    float s = bo[(size_t)i * DMODEL + j];
    for (int c = 0; c < DMODEL; c++) s += b[c] * w[(size_t)c * DMODEL + j];
    batt[(size_t)i * DMODEL + j] = s;
}

// ======================= add + layernorm =======================
__device__ __forceinline__ float block_reduce_sum(float v, float* sh) {
    #pragma unroll
    for (int o = 16; o > 0; o >>= 1) v += __shfl_xor_sync(0xffffffffu, v, o);
    __syncthreads();
    if ((threadIdx.x & 31) == 0) sh[threadIdx.x >> 5] = v;
    __syncthreads();
    float t = (threadIdx.x < 8) ? sh[threadIdx.x] : 0.f;
    if (threadIdx.x < 32) {
        #pragma unroll
        for (int o = 4; o > 0; o >>= 1) t += __shfl_xor_sync(0xffffffffu, t, o);
        if (threadIdx.x == 0) sh[0] = t;
    }
    __syncthreads();
    return sh[0];
}

__global__ void __launch_bounds__(256) add_ln(float* __restrict__ X, const float* __restrict__ O) {
    __shared__ float sh[8];
    const size_t base = (size_t)blockIdx.x * DMODEL;
    float v[3];
    float s = 0.f;
    #pragma unroll
    for (int j = 0; j < 3; j++) {
        int c = threadIdx.x + j * 256;
        float t = X[base + c] + O[base + c];
        v[j] = t; s += t;
    }
    float mu = block_reduce_sum(s, sh) * (1.f / DMODEL);
    float q = 0.f;
    #pragma unroll
    for (int j = 0; j < 3; j++) { float d = v[j] - mu; q += d * d; }
    float var = block_reduce_sum(q, sh) * (1.f / DMODEL);
    float inv = rsqrtf(var);
    #pragma unroll
    for (int j = 0; j < 3; j++) {
        int c = threadIdx.x + j * 256;
        X[base + c] = (v[j] - mu) * inv;
    }
}

// ======================= row softmax over VOCAB =======================
__global__ void __launch_bounds__(256) softmax_rows(float* __restrict__ X) {
    __shared__ float sh[8];
    const size_t base = (size_t)blockIdx.x * VOCAB;
    float v[32];
    float m = -INFINITY;
    #pragma unroll
    for (int j = 0; j < 32; j++) {
        v[j] = X[base + threadIdx.x + j * 256];
        m = fmaxf(m, v[j]);
    }
    #pragma unroll
    for (int o = 16; o > 0; o >>= 1) m = fmaxf(m, __shfl_xor_sync(0xffffffffu, m, o));
    if ((threadIdx.x & 31) == 0) sh[threadIdx.x >> 5] = m;
    __syncthreads();
    float mm = (threadIdx.x < 8) ? sh[threadIdx.x] : -INFINITY;
    if (threadIdx.x < 32) {
        #pragma unroll
        for (int o = 4; o > 0; o >>= 1) mm = fmaxf(mm, __shfl_xor_sync(0xffffffffu, mm, o));
        if (threadIdx.x == 0) sh[0] = mm;
    }
    __syncthreads();
    m = sh[0];
    __syncthreads();

    float s = 0.f;
    #pragma unroll
    for (int j = 0; j < 32; j++) { v[j] = expf(v[j] - m); s += v[j]; }
    float tot = block_reduce_sum(s, sh);
    float inv = 1.f / tot;
    #pragma unroll
    for (int j = 0; j < 32; j++) X[base + threadIdx.x + j * 256] = v[j] * inv;
}

// ======================= launch =======================
extern "C" void kernel_launch(void* const* d_in, const int* in_sizes, int n_in,
                              void* d_out, int out_size) {
    const float* Xin   = (const float*)d_in[0];
    const float* emb_w = (const float*)d_in[1];
    const float* emb_b = (const float*)d_in[2];
    // d_in[3..6] = Wq,bq,Wk,bk — mathematically unused (softmax row-sum == 1)
    const float* Wv    = (const float*)d_in[7];
    const float* bv    = (const float*)d_in[8];
    const float* Wo    = (const float*)d_in[9];
    const float* bo    = (const float*)d_in[10];
    const float* W1    = (const float*)d_in[11];
    const float* b1    = (const float*)d_in[12];
    const float* W2    = (const float*)d_in[13];
    const float* b2    = (const float*)d_in[14];
    const float* Wout  = (const float*)d_in[15];
    const float* bout  = (const float*)d_in[16];
    float* out = (float*)d_out;

    float *pX, *pTmp, *pF, *pWvr, *pWatt, *pBatt;
    cudaGetSymbolAddress((void**)&pX,    g_X);
    cudaGetSymbolAddress((void**)&pTmp,  g_tmp);
    cudaGetSymbolAddress((void**)&pF,    g_F);
    cudaGetSymbolAddress((void**)&pWvr,  g_Wvr);
    cudaGetSymbolAddress((void**)&pWatt, g_Watt);
    cudaGetSymbolAddress((void**)&pBatt, g_batt);

    // ---- fuse attention weights: Watt[i] = Wv_r[i] @ Wo[i]; batt[i] = bv[i]@Wo[i] + bo[i] ----
    prep_wv<<<(NBLOCKS * DMODEL * DMODEL + 255) / 256, 256>>>(Wv, pWvr);
    prep_batt<<<dim3(DMODEL / 256, NBLOCKS), 256>>>(bv, Wo, bo, pBatt);
    gemm_tf32<0, 1><<<dim3(DMODEL / 128, DMODEL / 128, NBLOCKS), 256>>>(
        pWvr, Wo, nullptr, pWatt, DMODEL, DMODEL, DMODEL);

    // ---- embedding: X = Xin @ emb_w + emb_b ----
    gemm_tf32<0, 0><<<dim3(DMODEL / 128, NTOK / 128), 256>>>(
        Xin, emb_w, emb_b, pX, NTOK, DMODEL, VOCAB);

    // ---- 4 transformer blocks (attention == fused V->O projection) ----
    for (int i = 0; i < NBLOCKS; i++) {
        gemm_tf32<0, 0><<<dim3(DMODEL / 128, NTOK / 128), 256>>>(
            pX, pWatt + (size_t)i * DMODEL * DMODEL, pBatt + (size_t)i * DMODEL,
            pTmp, NTOK, DMODEL, DMODEL);
        add_ln<<<NTOK, 256>>>(pX, pTmp);

        gemm_tf32<1, 0><<<dim3(HIDDEN / 128, NTOK / 128), 256>>>(
            pX, W1 + (size_t)i * DMODEL * HIDDEN, b1 + (size_t)i * HIDDEN,
            pTmp, NTOK, HIDDEN, DMODEL);
        gemm_tf32<0, 0><<<dim3(DMODEL / 128, NTOK / 128), 256>>>(
            pTmp, W2 + (size_t)i * HIDDEN * DMODEL, b2 + (size_t)i * DMODEL,
            pF, NTOK, DMODEL, HIDDEN);
        add_ln<<<NTOK, 256>>>(pX, pF);
    }

    // ---- output head + softmax (in-place on d_out) ----
    gemm_tf32<0, 0><<<dim3(VOCAB / 128, NTOK / 128), 256>>>(
        pX, Wout, bout, out, NTOK, VOCAB, DMODEL);
    softmax_rows<<<NTOK, 256>>>(out);
}

// round 4
// speedup vs baseline: 2.8120x; 2.0404x over previous
#include <cuda_runtime.h>
#include <cuda_bf16.h>
#include <math.h>
#include <stdint.h>

#define DMODEL 768
#define VOCAB  8192
#define HIDDEN 3072
#define NBLOCKS 4
#define NTOK   4096
#define NHEAD  12
#define DHEAD  64

// -------- scratch (static __device__ — no allocation allowed) --------
__device__ float g_X   [NTOK * DMODEL];
__device__ float g_tmp [NTOK * HIDDEN];
__device__ float g_F   [NTOK * DMODEL];
__device__ float g_Wvr [NBLOCKS * DMODEL * DMODEL];
__device__ float g_Watt[NBLOCKS * DMODEL * DMODEL];
__device__ float g_batt[NBLOCKS * DMODEL];

// ======================= helpers =======================
// pack two floats to bf16x2 (low half = f0)
__device__ __forceinline__ uint32_t pk_bf2(float f0, float f1) {
    uint32_t u;
    asm("cvt.rn.bf16x2.f32 %0, %1, %2;" : "=r"(u) : "f"(f1), "f"(f0));
    return u;
}

__device__ __forceinline__ void ldsm_x4(uint32_t* r, const void* p) {
    uint32_t a = (uint32_t)__cvta_generic_to_shared(p);
    asm volatile("ldmatrix.sync.aligned.m8n8.x4.shared.b16 {%0,%1,%2,%3}, [%4];"
                 : "=r"(r[0]), "=r"(r[1]), "=r"(r[2]), "=r"(r[3]) : "r"(a));
}
__device__ __forceinline__ void ldsm_x4_t(uint32_t* r, const void* p) {
    uint32_t a = (uint32_t)__cvta_generic_to_shared(p);
    asm volatile("ldmatrix.sync.aligned.m8n8.x4.trans.shared.b16 {%0,%1,%2,%3}, [%4];"
                 : "=r"(r[0]), "=r"(r[1]), "=r"(r[2]), "=r"(r[3]) : "r"(a));
}

__device__ __forceinline__ void mma_bf16(float* c, const uint32_t* a, const uint32_t* b) {
    asm volatile("mma.sync.aligned.m16n8k16.row.col.f32.bf16.bf16.f32 "
                 "{%0,%1,%2,%3}, {%4,%5,%6,%7}, {%8,%9}, {%0,%1,%2,%3};"
                 : "+f"(c[0]), "+f"(c[1]), "+f"(c[2]), "+f"(c[3])
                 : "r"(a[0]), "r"(a[1]), "r"(a[2]), "r"(a[3]),
                   "r"(b[0]), "r"(b[1]));
}

// ======================= GEMM: C = A[MxK] @ B[KxN] (+bias, opt relu) =======================
// 128x128x16 tiles, 8 warps, warp tile 32x64, mma.m16n8k16.bf16, hi/lo 3-pass split
// precomputed at load time. M,N multiples of 128; K multiple of 16.
#define BK 16
#define ASTR 24    // bf16 per A row: 16 + 8 pad -> 48B rows, 16B-aligned, LDSM conflict-free
#define BSTR 136   // bf16 per B row: 128 + 8 pad -> 272B rows, 16B-aligned, LDSM conflict-free

template<int RELU, int BATCHED>
__global__ void __launch_bounds__(256, 2) gemm_bf16x3(
    const float* __restrict__ A, const float* __restrict__ B,
    const float* __restrict__ bias, float* __restrict__ C,
    int M, int N, int K)
{
    __shared__ __nv_bfloat16 As[2][2][128][ASTR];  // [stage][hi/lo] = 24 KB
    __shared__ __nv_bfloat16 Bs[2][2][BK][BSTR];   // 17 KB

    if (BATCHED) {
        size_t z = blockIdx.z;
        A += z * (size_t)M * K;
        B += z * (size_t)K * N;
        C += z * (size_t)M * N;
    }

    const int tid  = threadIdx.x;
    const int lane = tid & 31;
    const int wid  = tid >> 5;
    const int wm   = wid & 3;     // 0..3 (M)
    const int wn   = wid >> 2;    // 0..1 (N)

    const float* Ab = A + (size_t)(blockIdx.y * 128) * K;
    const float* Bb = B + blockIdx.x * 128;

    // loader indices (2 iterations of 256 threads each)
    const int aRow0 = tid >> 2;          // +128? no: l = tid + i*256 -> row = l>>2
    (void)aRow0;

    float4 ra[2], rb[2];

    auto ldg_tile = [&](int kt) {
        #pragma unroll
        for (int i = 0; i < 2; i++) {
            int l = tid + i * 256;
            int row = l >> 2, c4 = (l & 3) * 4;
            ra[i] = *reinterpret_cast<const float4*>(Ab + (size_t)row * K + kt + c4);
        }
        #pragma unroll
        for (int i = 0; i < 2; i++) {
            int l = tid + i * 256;
            int row = l >> 5, c4 = (l & 31) * 4;
            rb[i] = *reinterpret_cast<const float4*>(Bb + (size_t)(kt + row) * N + c4);
        }
    };

    auto sts_tile = [&](int s) {
        #pragma unroll
        for (int i = 0; i < 2; i++) {
            int l = tid + i * 256;
            int row = l >> 2, c4 = (l & 3) * 4;
            float4 v = ra[i];
            uint32_t h0 = pk_bf2(v.x, v.y);
            uint32_t h1 = pk_bf2(v.z, v.w);
            float r0 = v.x - __uint_as_float(h0 << 16);
            float r1 = v.y - __uint_as_float(h0 & 0xffff0000u);
            float r2 = v.z - __uint_as_float(h1 << 16);
            float r3 = v.w - __uint_as_float(h1 & 0xffff0000u);
            uint32_t l0 = pk_bf2(r0, r1);
            uint32_t l1 = pk_bf2(r2, r3);
            *reinterpret_cast<uint2*>(&As[s][0][row][c4]) = make_uint2(h0, h1);
            *reinterpret_cast<uint2*>(&As[s][1][row][c4]) = make_uint2(l0, l1);
        }
        #pragma unroll
        for (int i = 0; i < 2; i++) {
            int l = tid + i * 256;
            int row = l >> 5, c4 = (l & 31) * 4;
            float4 v = rb[i];
            uint32_t h0 = pk_bf2(v.x, v.y);
            uint32_t h1 = pk_bf2(v.z, v.w);
            float r0 = v.x - __uint_as_float(h0 << 16);
            float r1 = v.y - __uint_as_float(h0 & 0xffff0000u);
            float r2 = v.z - __uint_as_float(h1 << 16);
            float r3 = v.w - __uint_as_float(h1 & 0xffff0000u);
            uint32_t l0 = pk_bf2(r0, r1);
            uint32_t l1 = pk_bf2(r2, r3);
            *reinterpret_cast<uint2*>(&Bs[s][0][row][c4]) = make_uint2(h0, h1);
            *reinterpret_cast<uint2*>(&Bs[s][1][row][c4]) = make_uint2(l0, l1);
        }
    };

    float acc[2][8][4];
    #pragma unroll
    for (int i = 0; i < 2; i++)
        #pragma unroll
        for (int j = 0; j < 8; j++)
            #pragma unroll
            for (int k = 0; k < 4; k++) acc[i][j][k] = 0.f;

    // fragment lane addressing
    const int fr  = lane & 15;            // row within 16 (A: m; B: k)
    const int fc8 = (lane >> 4) * 8;      // 0 or 8

    const int nk = K / BK;
    ldg_tile(0);

    for (int t = 0; t < nk; t++) {
        const int s = t & 1;
        sts_tile(s);
        __syncthreads();
        if (t + 1 < nk) ldg_tile((t + 1) * BK);

        uint32_t Ahi[2][4], Alo[2][4];
        #pragma unroll
        for (int mt = 0; mt < 2; mt++) {
            int r = wm * 32 + mt * 16 + fr;
            ldsm_x4(Ahi[mt], &As[s][0][r][fc8]);
            ldsm_x4(Alo[mt], &As[s][1][r][fc8]);
        }
        #pragma unroll
        for (int g = 0; g < 4; g++) {       // 16-wide n groups
            uint32_t Bhi[4], Blo[4];
            int nc = wn * 64 + g * 16 + fc8;
            ldsm_x4_t(Bhi, &Bs[s][0][fr][nc]);
            ldsm_x4_t(Blo, &Bs[s][1][fr][nc]);
            #pragma unroll
            for (int mt = 0; mt < 2; mt++) {
                #pragma unroll
                for (int h = 0; h < 2; h++) {   // n8 halves within group
                    float* c = acc[mt][g * 2 + h];
                    mma_bf16(c, Ahi[mt], Bhi + 2 * h);
                    mma_bf16(c, Alo[mt], Bhi + 2 * h);
                    mma_bf16(c, Ahi[mt], Blo + 2 * h);
                }
            }
        }
        __syncthreads();
    }

    // epilogue (same C-fragment layout as m16n8k8)
    const int rowC = blockIdx.y * 128 + wm * 32 + (lane >> 2);
    const int colC = blockIdx.x * 128 + wn * 64 + (lane & 3) * 2;
    float bv[8][2];
    #pragma unroll
    for (int nt = 0; nt < 8; nt++) {
        bv[nt][0] = bias ? bias[colC + nt * 8]     : 0.f;
        bv[nt][1] = bias ? bias[colC + nt * 8 + 1] : 0.f;
    }
    #pragma unroll
    for (int mt = 0; mt < 2; mt++) {
        int r0 = rowC + mt * 16;
        #pragma unroll
        for (int nt = 0; nt < 8; nt++) {
            int c = colC + nt * 8;
            float v00 = acc[mt][nt][0] + bv[nt][0];
            float v01 = acc[mt][nt][1] + bv[nt][1];
            float v10 = acc[mt][nt][2] + bv[nt][0];
            float v11 = acc[mt][nt][3] + bv[nt][1];
            if (RELU) {
                v00 = fmaxf(v00, 0.f); v01 = fmaxf(v01, 0.f);
                v10 = fmaxf(v10, 0.f); v11 = fmaxf(v11, 0.f);
            }
            *reinterpret_cast<float2*>(C + (size_t)r0 * N + c)       = make_float2(v00, v01);
            *reinterpret_cast<float2*>(C + (size_t)(r0 + 8) * N + c) = make_float2(v10, v11);
        }
    }
}

// ======================= weight prep =======================
__global__ void prep_wv(const float* __restrict__ Wv, float* __restrict__ Wvr) {
    int idx = blockIdx.x * blockDim.x + threadIdx.x;
    if (idx >= NBLOCKS * DMODEL * DMODEL) return;
    int i   = idx / (DMODEL * DMODEL);
    int rem = idx % (DMODEL * DMODEL);
    int d   = rem / DMODEL;
    int c   = rem % DMODEL;
    int h = c / DHEAD, e = c % DHEAD;
    Wvr[idx] = Wv[(((size_t)i * NHEAD + h) * DMODEL + d) * DHEAD + e];
}

__global__ void prep_batt(const float* __restrict__ bv, const float* __restrict__ Wo,
                          const float* __restrict__ bo, float* __restrict__ batt) {
    int i = blockIdx.y;
    int j = blockIdx.x * blockDim.x + threadIdx.x;
    if (j >= DMODEL) return;
    const float* w = Wo + (size_t)i * DMODEL * DMODEL;
    const float* b = bv + (size_t)i * DMODEL;
    float s = bo[(size_t)i * DMODEL + j];
    for (int c = 0; c < DMODEL; c++) s += b[c] * w[(size_t)c * DMODEL + j];
    batt[(size_t)i * DMODEL + j] = s;
}

// ======================= add + layernorm =======================
__device__ __forceinline__ float block_reduce_sum(float v, float* sh) {
    #pragma unroll
    for (int o = 16; o > 0; o >>= 1) v += __shfl_xor_sync(0xffffffffu, v, o);
    __syncthreads();
    if ((threadIdx.x & 31) == 0) sh[threadIdx.x >> 5] = v;
    __syncthreads();
    float t = (threadIdx.x < 8) ? sh[threadIdx.x] : 0.f;
    if (threadIdx.x < 32) {
        #pragma unroll
        for (int o = 4; o > 0; o >>= 1) t += __shfl_xor_sync(0xffffffffu, t, o);
        if (threadIdx.x == 0) sh[0] = t;
    }
    __syncthreads();
    return sh[0];
}

__global__ void __launch_bounds__(256) add_ln(float* __restrict__ X, const float* __restrict__ O) {
    __shared__ float sh[8];
    const size_t base = (size_t)blockIdx.x * DMODEL;
    float v[3];
    float s = 0.f;
    #pragma unroll
    for (int j = 0; j < 3; j++) {
        int c = threadIdx.x + j * 256;
        float t = X[base + c] + O[base + c];
        v[j] = t; s += t;
    }
    float mu = block_reduce_sum(s, sh) * (1.f / DMODEL);
    float q = 0.f;
    #pragma unroll
    for (int j = 0; j < 3; j++) { float d = v[j] - mu; q += d * d; }
    float var = block_reduce_sum(q, sh) * (1.f / DMODEL);
    float inv = rsqrtf(var);
    #pragma unroll
    for (int j = 0; j < 3; j++) {
        int c = threadIdx.x + j * 256;
        X[base + c] = (v[j] - mu) * inv;
    }
}

// ======================= row softmax over VOCAB =======================
__global__ void __launch_bounds__(256) softmax_rows(float* __restrict__ X) {
    __shared__ float sh[8];
    const size_t base = (size_t)blockIdx.x * VOCAB;
    float v[32];
    float m = -INFINITY;
    #pragma unroll
    for (int j = 0; j < 32; j++) {
        v[j] = X[base + threadIdx.x + j * 256];
        m = fmaxf(m, v[j]);
    }
    #pragma unroll
    for (int o = 16; o > 0; o >>= 1) m = fmaxf(m, __shfl_xor_sync(0xffffffffu, m, o));
    if ((threadIdx.x & 31) == 0) sh[threadIdx.x >> 5] = m;
    __syncthreads();
    float mm = (threadIdx.x < 8) ? sh[threadIdx.x] : -INFINITY;
    if (threadIdx.x < 32) {
        #pragma unroll
        for (int o = 4; o > 0; o >>= 1) mm = fmaxf(mm, __shfl_xor_sync(0xffffffffu, mm, o));
        if (threadIdx.x == 0) sh[0] = mm;
    }
    __syncthreads();
    m = sh[0];
    __syncthreads();

    float s = 0.f;
    #pragma unroll
    for (int j = 0; j < 32; j++) { v[j] = expf(v[j] - m); s += v[j]; }
    float tot = block_reduce_sum(s, sh);
    float inv = 1.f / tot;
    #pragma unroll
    for (int j = 0; j < 32; j++) X[base + threadIdx.x + j * 256] = v[j] * inv;
}

// ======================= launch =======================
extern "C" void kernel_launch(void* const* d_in, const int* in_sizes, int n_in,
                              void* d_out, int out_size) {
    const float* Xin   = (const float*)d_in[0];
    const float* emb_w = (const float*)d_in[1];
    const float* emb_b = (const float*)d_in[2];
    // d_in[3..6] = Wq,bq,Wk,bk — mathematically unused (softmax row-sum == 1)
    const float* Wv    = (const float*)d_in[7];
    const float* bv    = (const float*)d_in[8];
    const float* Wo    = (const float*)d_in[9];
    const float* bo    = (const float*)d_in[10];
    const float* W1    = (const float*)d_in[11];
    const float* b1    = (const float*)d_in[12];
    const float* W2    = (const float*)d_in[13];
    const float* b2    = (const float*)d_in[14];
    const float* Wout  = (const float*)d_in[15];
    const float* bout  = (const float*)d_in[16];
    float* out = (float*)d_out;

    float *pX, *pTmp, *pF, *pWvr, *pWatt, *pBatt;
    cudaGetSymbolAddress((void**)&pX,    g_X);
    cudaGetSymbolAddress((void**)&pTmp,  g_tmp);
    cudaGetSymbolAddress((void**)&pF,    g_F);
    cudaGetSymbolAddress((void**)&pWvr,  g_Wvr);
    cudaGetSymbolAddress((void**)&pWatt, g_Watt);
    cudaGetSymbolAddress((void**)&pBatt, g_batt);

    // ---- fuse attention weights: Watt[i] = Wv_r[i] @ Wo[i]; batt[i] = bv[i]@Wo[i] + bo[i] ----
    prep_wv<<<(NBLOCKS * DMODEL * DMODEL + 255) / 256, 256>>>(Wv, pWvr);
    prep_batt<<<dim3(DMODEL / 256, NBLOCKS), 256>>>(bv, Wo, bo, pBatt);
    gemm_bf16x3<0, 1><<<dim3(DMODEL / 128, DMODEL / 128, NBLOCKS), 256>>>(
        pWvr, Wo, nullptr, pWatt, DMODEL, DMODEL, DMODEL);

    // ---- embedding: X = Xin @ emb_w + emb_b ----
    gemm_bf16x3<0, 0><<<dim3(DMODEL / 128, NTOK / 128), 256>>>(
        Xin, emb_w, emb_b, pX, NTOK, DMODEL, VOCAB);

    // ---- 4 transformer blocks (attention == fused V->O projection) ----
    for (int i = 0; i < NBLOCKS; i++) {
        gemm_bf16x3<0, 0><<<dim3(DMODEL / 128, NTOK / 128), 256>>>(
            pX, pWatt + (size_t)i * DMODEL * DMODEL, pBatt + (size_t)i * DMODEL,
            pTmp, NTOK, DMODEL, DMODEL);
        add_ln<<<NTOK, 256>>>(pX, pTmp);

        gemm_bf16x3<1, 0><<<dim3(HIDDEN / 128, NTOK / 128), 256>>>(
            pX, W1 + (size_t)i * DMODEL * HIDDEN, b1 + (size_t)i * HIDDEN,
            pTmp, NTOK, HIDDEN, DMODEL);
        gemm_bf16x3<0, 0><<<dim3(DMODEL / 128, NTOK / 128), 256>>>(
            pTmp, W2 + (size_t)i * HIDDEN * DMODEL, b2 + (size_t)i * DMODEL,
            pF, NTOK, DMODEL, HIDDEN);
        add_ln<<<NTOK, 256>>>(pX, pF);
    }

    // ---- output head + softmax (in-place on d_out) ----
    gemm_bf16x3<0, 0><<<dim3(VOCAB / 128, NTOK / 128), 256>>>(
        pX, Wout, bout, out, NTOK, VOCAB, DMODEL);
    softmax_rows<<<NTOK, 256>>>(out);
}